// round 4
// baseline (speedup 1.0000x reference)
#include <cuda_runtime.h>
#include <cstdint>
#include <cstddef>

#define BS 256
#define KDIM 1024
#define NDIM 1024
#define NSTATES 20
#define TN 64        // n-columns per worker block (2 per lane)
#define RCH 16       // max rows (samples) per entry
#define KSPLIT 2
#define KHALF (KDIM / KSPLIT)   // 512 k per worker block
#define KC 256       // k elements staged per chunk (32KB smem)
#define NWARPS 8
#define KSLC (KC / NWARPS)      // 32 k per warp per chunk
#define NTHREADS 256
#define MAXE 36      // max entries: sum ceil(cnt_s/16) <= 16 + 20

// ---- device scratch (no allocations allowed) ----
__device__ int   g_rows[MAXE][RCH];
__device__ int   g_nrows[MAXE];
__device__ int   g_state[MAXE];
__device__ int   g_nentries;
__device__ float g_partial[KSPLIT][BS][NDIM];   // 2 MB

__device__ __forceinline__ unsigned long long mul2(unsigned long long a, unsigned long long b) {
    unsigned long long d;
    asm("mul.rn.f32x2 %0, %1, %2;" : "=l"(d) : "l"(a), "l"(b));
    return d;
}
__device__ __forceinline__ unsigned long long fma2(unsigned long long a, unsigned long long b, unsigned long long c) {
    unsigned long long d;
    asm("fma.rn.f32x2 %0, %1, %2, %3;" : "=l"(d) : "l"(a), "l"(b), "l"(c));
    return d;
}

// ---- kernel A: build compact work entries (1 block, 256 threads) ----
__global__ void build_entries_kernel(const int* __restrict__ state)
{
    __shared__ int st[BS];
    __shared__ int cnt[NSTATES];
    __shared__ int cbase[NSTATES + 1];

    const int t = threadIdx.x;
    const int s = state[t];
    st[t] = s;
    __syncthreads();

    int rank = 0;
    for (int j = 0; j < t; j++) rank += (st[j] == s);

    if (t < NSTATES) {
        int c = 0;
        for (int j = 0; j < BS; j++) c += (st[j] == t);
        cnt[t] = c;
    }
    __syncthreads();

    if (t == 0) {
        int b = 0;
        for (int i = 0; i < NSTATES; i++) {
            cbase[i] = b;
            b += (cnt[i] + RCH - 1) / RCH;
        }
        cbase[NSTATES] = b;
        g_nentries = b;
    }
    __syncthreads();

    const int e = cbase[s] + rank / RCH;
    g_rows[e][rank % RCH] = t;

    if (t < NSTATES) {
        const int nch = (cnt[t] + RCH - 1) / RCH;
        for (int c = 0; c < nch; c++) {
            g_nrows[cbase[t] + c] = min(cnt[t] - c * RCH, RCH);
            g_state[cbase[t] + c] = t;
        }
    }
}

// ---- kernel B: partial GEMM per (n-tile, entry, k-half) ----
__global__ __launch_bounds__(NTHREADS, 3)
void masked_dense_partial_kernel(const float* __restrict__ x,
                                 const float* __restrict__ kern,
                                 const float* __restrict__ masks)
{
    // 32KB dynamic smem: x chunk duplicated as f32x2 pairs [RCH][KC];
    // reused afterwards as the 8-warp reduction buffer [8][RCH*TN] floats.
    extern __shared__ unsigned long long xs2[];
    __shared__ int rowlist[RCH];
    __shared__ int meta[2];   // nrows, state

    const int e = blockIdx.y;
    if (e >= g_nentries) return;       // uniform exit, before any __syncthreads

    const int t = threadIdx.x;
    const int w = t >> 5;
    const int lane = t & 31;
    const int ks = blockIdx.z;
    const int n0 = blockIdx.x * TN;

    if (t < RCH) rowlist[t] = g_rows[e][t];
    if (t == RCH) meta[0] = g_nrows[e];
    if (t == RCH + 1) meta[1] = g_state[e];
    __syncthreads();
    const int nrows = meta[0];
    const int s = meta[1];

    unsigned long long acc[RCH];
#pragma unroll
    for (int r = 0; r < RCH; r++) acc[r] = 0ull;

    const int gc = n0 + 2 * lane;      // this lane's 2 global columns
    const int kbase0 = ks * KHALF;

    for (int kc = 0; kc < KHALF / KC; kc++) {
        if (kc > 0) __syncthreads();
        // stage x[rows][kbase0 + kc*KC : +KC], duplicated (v,v)
        {
            float4* xsf4 = (float4*)xs2;
            for (int e4 = t; e4 < RCH * (KC / 4); e4 += NTHREADS) {
                const int r = e4 >> 6;                    // KC/4 == 64
                const int k4 = (e4 & 63) * 4;
                float4 v;
                if (r < nrows)
                    v = *(const float4*)&x[(size_t)rowlist[r] * KDIM + kbase0 + kc * KC + k4];
                else
                    v = make_float4(0.f, 0.f, 0.f, 0.f);
                const int base = (r * KC + k4) >> 1;      // float4 index
                xsf4[base + 0] = make_float4(v.x, v.x, v.y, v.y);
                xsf4[base + 1] = make_float4(v.z, v.z, v.w, v.w);
            }
        }
        __syncthreads();

        const int kbase = kbase0 + kc * KC + w * KSLC;
        const float* mp = masks + ((size_t)s * KDIM + kbase) * NDIM + gc;
        const float* kp = kern + (size_t)kbase * NDIM + gc;
        const ulonglong2* xrow2 = (const ulonglong2*)(xs2 + w * KSLC);

        // pair-steps (2 k each), prefetch distance 2: 8 LDG.64 in flight
        constexpr int NP = KSLC / 2;   // 16
        unsigned long long mbuf[2][2], kbuf[2][2];
#pragma unroll
        for (int sl = 0; sl < 2; sl++)
#pragma unroll
            for (int j = 0; j < 2; j++) {
                const size_t off = (size_t)(sl * 2 + j) * NDIM;
                mbuf[sl][j] = *(const unsigned long long*)(mp + off);
                kbuf[sl][j] = *(const unsigned long long*)(kp + off);
            }
#pragma unroll
        for (int p = 0; p < NP; p++) {
            const int cur = p & 1;
            const unsigned long long w0 = mul2(mbuf[cur][0], kbuf[cur][0]);
            const unsigned long long w1 = mul2(mbuf[cur][1], kbuf[cur][1]);
            if (p + 2 < NP) {
#pragma unroll
                for (int j = 0; j < 2; j++) {
                    const size_t off = (size_t)((p + 2) * 2 + j) * NDIM;
                    mbuf[cur][j] = *(const unsigned long long*)(mp + off);
                    kbuf[cur][j] = *(const unsigned long long*)(kp + off);
                }
            }
#pragma unroll
            for (int r = 0; r < RCH; r++) {
                const ulonglong2 xv = xrow2[r * (KC / 2) + p];   // broadcast LDS.128
                acc[r] = fma2(xv.x, w0, acc[r]);
                acc[r] = fma2(xv.y, w1, acc[r]);
            }
        }
    }
    __syncthreads();   // all warps done with xs2 before overlay

    // cross-warp k-reduction via flat smem buffer [8][RCH*TN] floats (32KB)
    {
        unsigned long long* myb = xs2 + (size_t)w * (RCH * TN / 2);
#pragma unroll
        for (int r = 0; r < RCH; r++)
            myb[r * (TN / 2) + lane] = acc[r];
    }
    __syncthreads();

    const float* redf = (const float*)xs2;
    for (int e2 = t; e2 < nrows * TN; e2 += NTHREADS) {
        float v = 0.f;
#pragma unroll
        for (int ww = 0; ww < NWARPS; ww++) v += redf[ww * (RCH * TN) + e2];
        const int r = e2 >> 6;                    // TN == 64
        const int c = e2 & 63;
        g_partial[ks][rowlist[r]][n0 + c] = v;    // no relu yet
    }
}

// ---- kernel C: out = relu(p0 + p1) ----
__global__ void reduce_relu_kernel(float* __restrict__ out)
{
    const int i = blockIdx.x * blockDim.x + threadIdx.x;   // float4 index
    const float4 a = ((const float4*)g_partial[0])[i];
    const float4 b = ((const float4*)g_partial[1])[i];
    float4 o;
    o.x = fmaxf(a.x + b.x, 0.f);
    o.y = fmaxf(a.y + b.y, 0.f);
    o.z = fmaxf(a.z + b.z, 0.f);
    o.w = fmaxf(a.w + b.w, 0.f);
    ((float4*)out)[i] = o;
}

extern "C" void kernel_launch(void* const* d_in, const int* in_sizes, int n_in,
                              void* d_out, int out_size)
{
    const float* x = nullptr;
    const int* state = nullptr;
    const float* kern = nullptr;
    const float* masks = nullptr;
    for (int i = 0; i < n_in; i++) {
        switch (in_sizes[i]) {
            case BS * KDIM:             x = (const float*)d_in[i]; break;
            case BS:                    state = (const int*)d_in[i]; break;
            case KDIM * NDIM:           kern = (const float*)d_in[i]; break;
            case NSTATES * KDIM * NDIM: masks = (const float*)d_in[i]; break;
            default: break;
        }
    }
    float* out = (float*)d_out;

    const int smem_bytes = RCH * KC * (int)sizeof(unsigned long long);  // 32 KB
    static bool attr_set = false;
    if (!attr_set) {
        cudaFuncSetAttribute(masked_dense_partial_kernel,
                             cudaFuncAttributeMaxDynamicSharedMemorySize, smem_bytes);
        attr_set = true;
    }

    build_entries_kernel<<<1, NTHREADS>>>(state);

    dim3 grid(NDIM / TN, MAXE, KSPLIT);   // (16, 36, 2)
    masked_dense_partial_kernel<<<grid, NTHREADS, smem_bytes>>>(x, kern, masks);

    reduce_relu_kernel<<<(BS * NDIM / 4) / 256, 256>>>(out);
}

// round 5
// speedup vs baseline: 1.0209x; 1.0209x over previous
#include <cuda_runtime.h>
#include <cstdint>
#include <cstddef>

#define BS 256
#define KDIM 1024
#define NDIM 1024
#define NSTATES 20
#define TN 32        // n-columns per worker block (1 per lane)
#define RCH 16       // max rows (samples) per entry
#define KC 256       // k elements staged per chunk
#define KPAD 20      // padded k-row stride in floats (conflict-free, 16B-aligned)
#define NWARPS 8
#define KSLC (KC / NWARPS)   // 32 k per warp per chunk
#define NTHREADS 256
#define MAXE 36

// ---- device scratch ----
__device__ int g_rows[MAXE][RCH];
__device__ int g_nrows[MAXE];
__device__ int g_state[MAXE];
__device__ int g_nentries;

__device__ __forceinline__ unsigned long long fma2(unsigned long long a, unsigned long long b, unsigned long long c) {
    unsigned long long d;
    asm("fma.rn.f32x2 %0, %1, %2, %3;" : "=l"(d) : "l"(a), "l"(b), "l"(c));
    return d;
}
__device__ __forceinline__ unsigned long long dup2(float v) {
    unsigned long long d;
    unsigned u = __float_as_uint(v);
    asm("mov.b64 %0, {%1, %1};" : "=l"(d) : "r"(u));
    return d;
}

// ---- kernel A: build compact work entries (1 block, 256 threads, ~1us) ----
__global__ void build_entries_kernel(const int* __restrict__ state)
{
    __shared__ int cnt[NWARPS][NSTATES];
    __shared__ int ebase[NSTATES];
    __shared__ int stot[NSTATES];

    const int t = threadIdx.x;
    const int w = t >> 5;
    const int lane = t & 31;

    if (t < NWARPS * NSTATES) ((int*)cnt)[t] = 0;
    __syncthreads();

    const int s = state[t];
    const unsigned grp = __match_any_sync(0xffffffffu, s);
    const int lr = __popc(grp & ((1u << lane) - 1u));
    if (lr == 0) cnt[w][s] = __popc(grp);
    __syncthreads();

    if (t < NSTATES) {
        int tot = 0;
#pragma unroll
        for (int ww = 0; ww < NWARPS; ww++) tot += cnt[ww][t];
        stot[t] = tot;
    }
    __syncthreads();

    if (t == 0) {
        int b = 0;
        for (int i = 0; i < NSTATES; i++) {
            ebase[i] = b;
            b += (stot[i] + RCH - 1) / RCH;
        }
        g_nentries = b;
    }
    __syncthreads();

    int before = 0;
    for (int w2 = 0; w2 < w; w2++) before += cnt[w2][s];
    const int rank = before + lr;
    const int e = ebase[s] + (rank >> 4);
    g_rows[e][rank & 15] = t;

    if (t < NSTATES) {
        const int nch = (stot[t] + RCH - 1) / RCH;
        for (int c = 0; c < nch; c++) {
            g_nrows[ebase[t] + c] = min(stot[t] - c * RCH, RCH);
            g_state[ebase[t] + c] = t;
        }
    }
}

// ---- kernel B: out tile per (n-tile, entry) ----
__global__ __launch_bounds__(NTHREADS, 4)
void masked_dense_kernel(const float* __restrict__ x,
                         const float* __restrict__ kern,
                         const float* __restrict__ masks,
                         float* __restrict__ out)
{
    // dynamic smem (20.5KB): x transposed [KC][KPAD] floats;
    // reused afterwards as reduction buffer [8 warps][8 pairs][32 lanes] u64 (16KB).
    extern __shared__ float xs[];
    __shared__ int rowlist[RCH];
    __shared__ int meta[2];   // nrows, state

    const int e = blockIdx.y;
    if (e >= g_nentries) return;       // uniform exit, before any __syncthreads

    const int t = threadIdx.x;
    const int w = t >> 5;
    const int lane = t & 31;
    const int n0 = blockIdx.x * TN;

    if (t < RCH) rowlist[t] = g_rows[e][t];
    if (t == RCH) meta[0] = g_nrows[e];
    if (t == RCH + 1) meta[1] = g_state[e];
    __syncthreads();
    const int nrows = meta[0];
    const int s = meta[1];

    // acc[j] packs (row 2j, row 2j+1) for this lane's single column
    unsigned long long acc[8];
#pragma unroll
    for (int j = 0; j < 8; j++) acc[j] = 0ull;

    const int gc = n0 + lane;          // this lane's global column

    for (int kc = 0; kc < KDIM / KC; kc++) {
        if (kc > 0) __syncthreads();
        // stage x[rows][kc*KC:+KC] TRANSPOSED into xs[k][r]
        for (int e4 = t; e4 < RCH * (KC / 4); e4 += NTHREADS) {
            const int r = e4 & 15;
            const int kq = e4 >> 4;            // k-quad 0..63
            float4 v;
            if (r < nrows)
                v = *(const float4*)&x[(size_t)rowlist[r] * KDIM + kc * KC + kq * 4];
            else
                v = make_float4(0.f, 0.f, 0.f, 0.f);
            xs[(kq * 4 + 0) * KPAD + r] = v.x;
            xs[(kq * 4 + 1) * KPAD + r] = v.y;
            xs[(kq * 4 + 2) * KPAD + r] = v.z;
            xs[(kq * 4 + 3) * KPAD + r] = v.w;
        }
        __syncthreads();

        // warp w handles k in [kbase, kbase+KSLC)
        const int kbase = kc * KC + w * KSLC;
        const float* mp = masks + ((size_t)s * KDIM + kbase) * NDIM + gc;
        const float* kp = kern + (size_t)kbase * NDIM + gc;
        const float* xw = xs + (w * KSLC) * KPAD;

        // groups of 4 k, prefetch distance 2 (16 LDG.32 in flight)
        constexpr int NG = KSLC / 4;   // 8
        float mb[2][4], kb[2][4];
#pragma unroll
        for (int sl = 0; sl < 2; sl++)
#pragma unroll
            for (int j = 0; j < 4; j++) {
                mb[sl][j] = mp[(size_t)(sl * 4 + j) * NDIM];
                kb[sl][j] = kp[(size_t)(sl * 4 + j) * NDIM];
            }
#pragma unroll
        for (int g = 0; g < NG; g++) {
            const int cur = g & 1;
            unsigned long long wp[4];
#pragma unroll
            for (int j = 0; j < 4; j++) wp[j] = dup2(mb[cur][j] * kb[cur][j]);
            if (g + 2 < NG) {
#pragma unroll
                for (int j = 0; j < 4; j++) {
                    mb[cur][j] = mp[(size_t)((g + 2) * 4 + j) * NDIM];
                    kb[cur][j] = kp[(size_t)((g + 2) * 4 + j) * NDIM];
                }
            }
#pragma unroll
            for (int j = 0; j < 4; j++) {
                // 4 broadcast LDS.128: 16 rows for k = g*4+j
                const ulonglong2* xk = (const ulonglong2*)(xw + (g * 4 + j) * KPAD);
                const ulonglong2 p01 = xk[0];   // rows 0-3
                const ulonglong2 p23 = xk[1];   // rows 4-7
                const ulonglong2 p45 = xk[2];   // rows 8-11
                const ulonglong2 p67 = xk[3];   // rows 12-15
                acc[0] = fma2(p01.x, wp[j], acc[0]);
                acc[1] = fma2(p01.y, wp[j], acc[1]);
                acc[2] = fma2(p23.x, wp[j], acc[2]);
                acc[3] = fma2(p23.y, wp[j], acc[3]);
                acc[4] = fma2(p45.x, wp[j], acc[4]);
                acc[5] = fma2(p45.y, wp[j], acc[5]);
                acc[6] = fma2(p67.x, wp[j], acc[6]);
                acc[7] = fma2(p67.y, wp[j], acc[7]);
            }
        }
    }
    __syncthreads();   // all warps done reading xs before overlay

    // cross-warp k-reduction: red[w][j][lane] as u64 pairs (16KB overlay)
    {
        unsigned long long* red = (unsigned long long*)xs;
#pragma unroll
        for (int j = 0; j < 8; j++)
            red[(w * 8 + j) * 32 + lane] = acc[j];
    }
    __syncthreads();

    const float* redf = (const float*)xs;
    for (int e2 = t; e2 < nrows * TN; e2 += NTHREADS) {
        const int r = e2 >> 5;
        const int c = e2 & 31;
        const int j = r >> 1;
        const int h = r & 1;
        float v = 0.f;
#pragma unroll
        for (int ww = 0; ww < NWARPS; ww++)
            v += redf[(((ww * 8 + j) * 32 + c) << 1) + h];
        out[(size_t)rowlist[r] * NDIM + n0 + c] = fmaxf(v, 0.f);
    }
}

extern "C" void kernel_launch(void* const* d_in, const int* in_sizes, int n_in,
                              void* d_out, int out_size)
{
    const float* x = nullptr;
    const int* state = nullptr;
    const float* kern = nullptr;
    const float* masks = nullptr;
    for (int i = 0; i < n_in; i++) {
        switch (in_sizes[i]) {
            case BS * KDIM:             x = (const float*)d_in[i]; break;
            case BS:                    state = (const int*)d_in[i]; break;
            case KDIM * NDIM:           kern = (const float*)d_in[i]; break;
            case NSTATES * KDIM * NDIM: masks = (const float*)d_in[i]; break;
            default: break;
        }
    }
    float* out = (float*)d_out;

    const int smem_bytes = KC * KPAD * (int)sizeof(float);   // 20480 B
    static bool attr_set = false;
    if (!attr_set) {
        cudaFuncSetAttribute(masked_dense_kernel,
                             cudaFuncAttributeMaxDynamicSharedMemorySize, smem_bytes);
        attr_set = true;
    }

    build_entries_kernel<<<1, NTHREADS>>>(state);

    dim3 grid(NDIM / TN, MAXE);   // (32, 36)
    masked_dense_kernel<<<grid, NTHREADS, smem_bytes>>>(x, kern, masks, out);
}

// round 7
// speedup vs baseline: 1.0253x; 1.0043x over previous
#include <cuda_runtime.h>
#include <cstdint>
#include <cstddef>

#define BS 256
#define KDIM 1024
#define NDIM 1024
#define NSTATES 20
#define TN 32        // n-columns per worker block (1 per lane)
#define RCH 16       // max rows (samples) per entry
#define KC 256       // k elements staged per chunk
#define KPAD 20      // padded k-row stride in floats (conflict-free, 16B-aligned)
#define NWARPS 8
#define KSLC (KC / NWARPS)   // 32 k per warp per chunk
#define NTHREADS 256
#define MAXE 36

// ---- device scratch ----
__device__ int g_rows[MAXE][RCH];
__device__ int g_nrows[MAXE];
__device__ int g_state[MAXE];
__device__ int g_nentries;

__device__ __forceinline__ unsigned long long fma2(unsigned long long a, unsigned long long b, unsigned long long c) {
    unsigned long long d;
    asm("fma.rn.f32x2 %0, %1, %2, %3;" : "=l"(d) : "l"(a), "l"(b), "l"(c));
    return d;
}
__device__ __forceinline__ unsigned long long dup2(float v) {
    unsigned long long d;
    unsigned u = __float_as_uint(v);
    asm("mov.b64 %0, {%1, %1};" : "=l"(d) : "r"(u));
    return d;
}

// ---- kernel A: build compact work entries (1 block, 256 threads, ~1us) ----
__global__ void build_entries_kernel(const int* __restrict__ state)
{
    __shared__ int cnt[NWARPS][NSTATES];
    __shared__ int ebase[NSTATES];
    __shared__ int stot[NSTATES];

    const int t = threadIdx.x;
    const int w = t >> 5;
    const int lane = t & 31;

    if (t < NWARPS * NSTATES) ((int*)cnt)[t] = 0;
    __syncthreads();

    const int s = state[t];
    const unsigned grp = __match_any_sync(0xffffffffu, s);
    const int lr = __popc(grp & ((1u << lane) - 1u));
    if (lr == 0) cnt[w][s] = __popc(grp);
    __syncthreads();

    if (t < NSTATES) {
        int tot = 0;
#pragma unroll
        for (int ww = 0; ww < NWARPS; ww++) tot += cnt[ww][t];
        stot[t] = tot;
    }
    __syncthreads();

    if (t == 0) {
        int b = 0;
        for (int i = 0; i < NSTATES; i++) {
            ebase[i] = b;
            b += (stot[i] + RCH - 1) / RCH;
        }
        g_nentries = b;
    }
    __syncthreads();

    int before = 0;
    for (int w2 = 0; w2 < w; w2++) before += cnt[w2][s];
    const int rank = before + lr;
    const int e = ebase[s] + (rank >> 4);
    g_rows[e][rank & 15] = t;

    if (t < NSTATES) {
        const int nch = (stot[t] + RCH - 1) / RCH;
        for (int c = 0; c < nch; c++) {
            g_nrows[ebase[t] + c] = min(stot[t] - c * RCH, RCH);
            g_state[ebase[t] + c] = t;
        }
    }
}

// ---- kernel B: out tile per (n-tile, entry) ----
__global__ __launch_bounds__(NTHREADS, 4)
void masked_dense_kernel(const float* __restrict__ x,
                         const float* __restrict__ kern,
                         const float* __restrict__ masks,
                         float* __restrict__ out)
{
    // dynamic smem (20.5KB): x transposed [KC][KPAD] floats;
    // reused afterwards as reduction buffer [8 warps][8 pairs][32 lanes] u64 (16KB).
    extern __shared__ float xs[];
    __shared__ int rowlist[RCH];
    __shared__ int meta[2];   // nrows, state

    const int e = blockIdx.y;
    if (e >= g_nentries) return;       // uniform exit, before any __syncthreads

    const int t = threadIdx.x;
    const int w = t >> 5;
    const int lane = t & 31;
    const int n0 = blockIdx.x * TN;

    if (t < RCH) rowlist[t] = g_rows[e][t];
    if (t == RCH) meta[0] = g_nrows[e];
    if (t == RCH + 1) meta[1] = g_state[e];
    __syncthreads();
    const int nrows = meta[0];
    const int s = meta[1];

    // acc[j] packs (row 2j, row 2j+1) for this lane's single column
    unsigned long long acc[8];
#pragma unroll
    for (int j = 0; j < 8; j++) acc[j] = 0ull;

    const int gc = n0 + lane;          // this lane's global column

    for (int kc = 0; kc < KDIM / KC; kc++) {
        if (kc > 0) __syncthreads();
        // stage x[rows][kc*KC:+KC] TRANSPOSED into xs[k][r]
        for (int e4 = t; e4 < RCH * (KC / 4); e4 += NTHREADS) {
            const int r = e4 & 15;
            const int kq = e4 >> 4;            // k-quad 0..63
            float4 v;
            if (r < nrows)
                v = *(const float4*)&x[(size_t)rowlist[r] * KDIM + kc * KC + kq * 4];
            else
                v = make_float4(0.f, 0.f, 0.f, 0.f);
            xs[(kq * 4 + 0) * KPAD + r] = v.x;
            xs[(kq * 4 + 1) * KPAD + r] = v.y;
            xs[(kq * 4 + 2) * KPAD + r] = v.z;
            xs[(kq * 4 + 3) * KPAD + r] = v.w;
        }
        __syncthreads();

        // warp w handles k in [kbase, kbase+KSLC)
        const int kbase = kc * KC + w * KSLC;
        const float* mp = masks + ((size_t)s * KDIM + kbase) * NDIM + gc;
        const float* kp = kern + (size_t)kbase * NDIM + gc;
        const float* xw = xs + (w * KSLC) * KPAD;

        // groups of 4 k, prefetch distance 2 (16 LDG.32 in flight)
        constexpr int NG = KSLC / 4;   // 8
        float mb[2][4], kb[2][4];
#pragma unroll
        for (int sl = 0; sl < 2; sl++)
#pragma unroll
            for (int j = 0; j < 4; j++) {
                mb[sl][j] = mp[(size_t)(sl * 4 + j) * NDIM];
                kb[sl][j] = kp[(size_t)(sl * 4 + j) * NDIM];
            }
#pragma unroll
        for (int g = 0; g < NG; g++) {
            const int cur = g & 1;
            unsigned long long wp[4];
#pragma unroll
            for (int j = 0; j < 4; j++) wp[j] = dup2(mb[cur][j] * kb[cur][j]);
            if (g + 2 < NG) {
#pragma unroll
                for (int j = 0; j < 4; j++) {
                    mb[cur][j] = mp[(size_t)((g + 2) * 4 + j) * NDIM];
                    kb[cur][j] = kp[(size_t)((g + 2) * 4 + j) * NDIM];
                }
            }
#pragma unroll
            for (int j = 0; j < 4; j++) {
                // 4 broadcast LDS.128: 16 rows for k = g*4+j
                const ulonglong2* xk = (const ulonglong2*)(xw + (g * 4 + j) * KPAD);
                const ulonglong2 p01 = xk[0];   // rows 0-3
                const ulonglong2 p23 = xk[1];   // rows 4-7
                const ulonglong2 p45 = xk[2];   // rows 8-11
                const ulonglong2 p67 = xk[3];   // rows 12-15
                acc[0] = fma2(p01.x, wp[j], acc[0]);
                acc[1] = fma2(p01.y, wp[j], acc[1]);
                acc[2] = fma2(p23.x, wp[j], acc[2]);
                acc[3] = fma2(p23.y, wp[j], acc[3]);
                acc[4] = fma2(p45.x, wp[j], acc[4]);
                acc[5] = fma2(p45.y, wp[j], acc[5]);
                acc[6] = fma2(p67.x, wp[j], acc[6]);
                acc[7] = fma2(p67.y, wp[j], acc[7]);
            }
        }
    }
    __syncthreads();   // all warps done reading xs before overlay

    // cross-warp k-reduction: red[w][j][lane] as u64 pairs (16KB overlay)
    {
        unsigned long long* red = (unsigned long long*)xs;
#pragma unroll
        for (int j = 0; j < 8; j++)
            red[(w * 8 + j) * 32 + lane] = acc[j];
    }
    __syncthreads();

    const float* redf = (const float*)xs;
    for (int e2 = t; e2 < nrows * TN; e2 += NTHREADS) {
        const int r = e2 >> 5;
        const int c = e2 & 31;
        const int j = r >> 1;
        const int h = r & 1;
        float v = 0.f;
#pragma unroll
        for (int ww = 0; ww < NWARPS; ww++)
            v += redf[(((ww * 8 + j) * 32 + c) << 1) + h];
        out[(size_t)rowlist[r] * NDIM + n0 + c] = fmaxf(v, 0.f);
    }
}

extern "C" void kernel_launch(void* const* d_in, const int* in_sizes, int n_in,
                              void* d_out, int out_size)
{
    const float* x = nullptr;
    const int* state = nullptr;
    const float* kern = nullptr;
    const float* masks = nullptr;
    for (int i = 0; i < n_in; i++) {
        switch (in_sizes[i]) {
            case BS * KDIM:             x = (const float*)d_in[i]; break;
            case BS:                    state = (const int*)d_in[i]; break;
            case KDIM * NDIM:           kern = (const float*)d_in[i]; break;
            case NSTATES * KDIM * NDIM: masks = (const float*)d_in[i]; break;
            default: break;
        }
    }
    float* out = (float*)d_out;

    const int smem_bytes = KC * KPAD * (int)sizeof(float);   // 20480 B
    static bool attr_set = false;
    if (!attr_set) {
        cudaFuncSetAttribute(masked_dense_kernel,
                             cudaFuncAttributeMaxDynamicSharedMemorySize, smem_bytes);
        attr_set = true;
    }

    build_entries_kernel<<<1, NTHREADS>>>(state);

    dim3 grid(NDIM / TN, MAXE);   // (32, 36)
    masked_dense_kernel<<<grid, NTHREADS, smem_bytes>>>(x, kern, masks, out);
}